// round 8
// baseline (speedup 1.0000x reference)
#include <cuda_runtime.h>
#include <cstdint>
#include <algorithm>

// Problem constants
#define NROWS   16          // only b=0 rows matter for the output
#define CTOT    384
#define NG      16          // channel groups
#define CPG     24          // channels per group (384/16)
#define HW      1024        // 32*32
#define KSEL    20
#define PTOT    96
#define NREM    76          // P - K
#define NUNSEL  1004        // 1024 - 20

struct Perm76 { int v[NREM]; };

// per-group score partials: [group][row][pixel] (1 MB, every slot written once)
__device__ float g_partial[NG][NROWS][HW];
// per-row completion counters (zero at load; reset by last block each launch)
__device__ int   g_cnt[NROWS];

// top-k shared arrays, overlaid on the conv tap planes (9.3 KB << 41.6 KB)
struct TK {
    unsigned int        hist1[256];
    unsigned int        hist2[256];
    unsigned long long  candkey[256];
    unsigned char       selflag[1024];
    short               slot_of_rank[NUNSEL];
    int                 warpsum[8];
    unsigned int        ccnt;
    int                 T1, T2, need2;
};

// find max bucket T with suffix count >= need; also count strictly above T.
// warp0 only; all lanes return identical T / cntAbove.
__device__ __forceinline__ void find_thresh(const unsigned int* hist, int need, int lane,
                                            int& T, int& cntAbove)
{
    const int base = lane * 8;
    unsigned int h[8], ls[8];
    #pragma unroll
    for (int j = 0; j < 8; ++j) h[j] = hist[base + j];
    ls[7] = h[7];
    #pragma unroll
    for (int j = 6; j >= 0; --j) ls[j] = ls[j + 1] + h[j];
    unsigned int tot = ls[0], s = tot;
    #pragma unroll
    for (int off = 1; off < 32; off <<= 1) {
        unsigned int o = __shfl_down_sync(0xffffffffu, s, off);
        if (lane + off < 32) s += o;
    }
    unsigned int hi = s - tot;          // totals of lanes strictly above this lane
    int best = -1;
    #pragma unroll
    for (int j = 7; j >= 0; --j)
        if (best < 0 && hi + ls[j] >= (unsigned int)need) best = base + j;
    #pragma unroll
    for (int off = 16; off; off >>= 1)
        best = max(best, __shfl_down_sync(0xffffffffu, best, off));
    best = __shfl_sync(0xffffffffu, best, 0);
    T = best;
    unsigned int c = 0;
    if (base > T)          c = tot;
    else if (base + 7 > T) c = ls[T - base + 1];
    #pragma unroll
    for (int off = 16; off; off >>= 1)
        c += __shfl_xor_sync(0xffffffffu, c, off);
    cntAbove = (int)c;
}

// ---------------------------------------------------------------------------
// Fused kernel: R7 conv structure + last-block-per-row two-level-radix top-k
// ---------------------------------------------------------------------------
__global__ void __launch_bounds__(256) fused_kernel(
    const float* __restrict__ feat,
    const float* __restrict__ dw_w,
    const float* __restrict__ pw_w,
    float* __restrict__ out,
    Perm76 perm)
{
    const int grp = blockIdx.x;     // 0..15
    const int row = blockIdx.y;     // 0..15
    const int t   = threadIdx.x;    // 0..255
    const int lane = t & 31, wrp = t >> 5;
    const int p0  = t * 4;
    const int x4  = p0 & 31;
    const int y   = p0 >> 5;

    __shared__ union { float P[9][34 * 34]; TK tk; } sm;   // 41.6 KB
    __shared__ unsigned long long wp[CPG][9];              // packed (w,w) weights
    __shared__ int isLast;

    // ---- conv phase (identical math to R7) --------------------------------
    for (int i = t; i < 9 * 34 * 34; i += 256) (&sm.P[0][0])[i] = 0.f;
    for (int i = t; i < CPG * 9; i += 256) {
        int ci = i / 9, k = i % 9, c = grp * CPG + ci;
        float w = pw_w[c] * dw_w[c * 9 + k];
        unsigned int u = __float_as_uint(w);
        wp[ci][k] = ((unsigned long long)u << 32) | (unsigned long long)u;
    }
    __syncthreads();

    const ulonglong2* base = reinterpret_cast<const ulonglong2*>(
        feat + ((size_t)row * CTOT + (size_t)grp * CPG) * HW) + t;

    unsigned long long accA[9], accB[9];
    #pragma unroll
    for (int k = 0; k < 9; ++k) { accA[k] = 0ull; accB[k] = 0ull; }

    #pragma unroll 4
    for (int c = 0; c < CPG; ++c) {
        ulonglong2 f = base[c * 256];            // 4 pixels (2x f32x2)
        #pragma unroll
        for (int k = 0; k < 9; ++k) {
            unsigned long long w = wp[c][k];
            asm("fma.rn.f32x2 %0, %1, %2, %0;" : "+l"(accA[k]) : "l"(f.x), "l"(w));
            asm("fma.rn.f32x2 %0, %1, %2, %0;" : "+l"(accB[k]) : "l"(f.y), "l"(w));
        }
    }

    #pragma unroll
    for (int k = 0; k < 9; ++k) {
        float* pr = &sm.P[k][(y + 1) * 34 + (x4 + 1)];
        pr[0] = __uint_as_float((unsigned int)(accA[k]));
        pr[1] = __uint_as_float((unsigned int)(accA[k] >> 32));
        pr[2] = __uint_as_float((unsigned int)(accB[k]));
        pr[3] = __uint_as_float((unsigned int)(accB[k] >> 32));
    }
    __syncthreads();

    float s0 = 0.f, s1 = 0.f, s2 = 0.f, s3 = 0.f;
    #pragma unroll
    for (int ky = 0; ky < 3; ++ky)
        #pragma unroll
        for (int kx = 0; kx < 3; ++kx) {
            const float* pr = &sm.P[ky * 3 + kx][(y + ky) * 34 + x4 + kx];
            s0 += pr[0]; s1 += pr[1]; s2 += pr[2]; s3 += pr[3];
        }

    __stcg(reinterpret_cast<float4*>(&g_partial[grp][row][p0]),
           make_float4(s0, s1, s2, s3));

    // ---- last-block handoff ----------------------------------------------
    __threadfence();
    if (t == 0) isLast = (atomicAdd(&g_cnt[row], 1) == NG - 1) ? 1 : 0;
    __syncthreads();            // also: all P reads complete -> TK overlay safe
    if (!isLast) return;
    if (t == 0) g_cnt[row] = 0; // reset for next launch (deterministic)
    __threadfence();            // acquire: partials visible before ldcg reads

    // ---- top-k phase (256 threads, 4 pixels each) -------------------------
    // sum the 16 group partials, ascending g (bit-identical to R7 topk)
    float4 acc4 = make_float4(0.f, 0.f, 0.f, 0.f);
    #pragma unroll
    for (int g = 0; g < NG; ++g) {
        float4 f = __ldcg(reinterpret_cast<const float4*>(&g_partial[g][row][p0]));
        acc4.x += f.x; acc4.y += f.y; acc4.z += f.z; acc4.w += f.w;
    }
    float v[4] = { acc4.x, acc4.y, acc4.z, acc4.w };
    unsigned int ordv[4];
    unsigned long long keyv[4];
    #pragma unroll
    for (int j = 0; j < 4; ++j) {
        unsigned int bits = __float_as_uint(v[j]);
        ordv[j] = (bits & 0x80000000u) ? ~bits : (bits | 0x80000000u);
        keyv[j] = ((unsigned long long)ordv[j] << 32) | (unsigned int)(1023 - (p0 + j));
    }

    sm.tk.hist1[t] = 0u;
    sm.tk.hist2[t] = 0u;
    reinterpret_cast<unsigned int*>(sm.tk.selflag)[t] = 0u;
    if (t == 0) sm.tk.ccnt = 0u;
    for (int i = t; i < NUNSEL; i += 256) sm.tk.slot_of_rank[i] = -1;
    __syncthreads();
    if (t < NREM) sm.tk.slot_of_rank[perm.v[t]] = (short)t;

    #pragma unroll
    for (int j = 0; j < 4; ++j) atomicAdd(&sm.tk.hist1[ordv[j] >> 24], 1u);
    __syncthreads();

    if (t < 32) {
        int T1, cA;
        find_thresh(sm.tk.hist1, KSEL, lane, T1, cA);
        if (lane == 0) { sm.tk.T1 = T1; sm.tk.need2 = KSEL - cA; }
    }
    __syncthreads();

    const int T1 = sm.tk.T1;
    #pragma unroll
    for (int j = 0; j < 4; ++j)
        if ((int)(ordv[j] >> 24) == T1)
            atomicAdd(&sm.tk.hist2[(ordv[j] >> 16) & 0xFFu], 1u);
    __syncthreads();

    if (t < 32) {
        int T2, cA2;
        find_thresh(sm.tk.hist2, sm.tk.need2, lane, T2, cA2);
        if (lane == 0) sm.tk.T2 = T2;
    }
    __syncthreads();

    const int T2 = sm.tk.T2;
    #pragma unroll
    for (int j = 0; j < 4; ++j) {
        int b1 = (int)(ordv[j] >> 24);
        bool cand = (b1 > T1) || (b1 == T1 && (int)((ordv[j] >> 16) & 0xFFu) >= T2);
        if (cand) {
            unsigned int pos = atomicAdd(&sm.tk.ccnt, 1u);
            sm.tk.candkey[pos & 255u] = keyv[j];   // nc << 256 by construction
        }
    }
    __syncthreads();

    // exact rank among candidates == exact global rank (desc value, asc index)
    const int nc = (int)sm.tk.ccnt;
    if (t < nc) {
        unsigned long long my = sm.tk.candkey[t];
        int rank = 0;
        for (int j = 0; j < nc; ++j) rank += (sm.tk.candkey[j] > my);
        if (rank < KSEL) {
            int idx = 1023 - (int)(my & 0xFFFFFFFFu);
            sm.tk.selflag[idx] = 1;
            int xc = idx & 31, yc = idx >> 5;
            xc = max(xc, 1); yc = max(yc, 1);
            out[row * PTOT + rank] = (float)xc;
            out[NROWS * PTOT + row * PTOT + rank] = (float)yc;
        }
    }
    __syncthreads();

    // rank among unselected (ascending pixel index == stable argsort of mask)
    unsigned int f4 = reinterpret_cast<const unsigned int*>(sm.tk.selflag)[t];
    int aj[4], cnt = 0;
    #pragma unroll
    for (int j = 0; j < 4; ++j) { aj[j] = ((f4 >> (8 * j)) & 0xFFu) ? 0 : 1; cnt += aj[j]; }
    int inc = cnt;
    #pragma unroll
    for (int off = 1; off < 32; off <<= 1) {
        int o = __shfl_up_sync(0xffffffffu, inc, off);
        if (lane >= off) inc += o;
    }
    if (lane == 31) sm.tk.warpsum[wrp] = inc;
    __syncthreads();
    int wbase = 0;
    for (int i = 0; i < wrp; ++i) wbase += sm.tk.warpsum[i];
    int rank = wbase + inc - cnt;

    #pragma unroll
    for (int j = 0; j < 4; ++j) {
        if (aj[j]) {
            int s = sm.tk.slot_of_rank[rank];
            ++rank;
            if (s >= 0) {
                int p = p0 + j;
                int xc = p & 31, yc = p >> 5;
                xc = max(xc, 1); yc = max(yc, 1);
                out[row * PTOT + KSEL + s] = (float)xc;
                out[NROWS * PTOT + row * PTOT + KSEL + s] = (float)yc;
            }
        }
    }
}

// ---------------------------------------------------------------------------
// Host: replicate jax.random.permutation(jax.random.key(42), 1004)[:76]
// (threefry2x32, partitionable: foldlike split + xor random_bits)
// ---------------------------------------------------------------------------
static inline uint32_t rotl32(uint32_t v, int d) { return (v << d) | (v >> (32 - d)); }

static void threefry2x32_host(uint32_t k0, uint32_t k1, uint32_t c0, uint32_t c1,
                              uint32_t* o0, uint32_t* o1)
{
    uint32_t ks[3] = { k0, k1, k0 ^ k1 ^ 0x1BD11BDAu };
    static const int rot[2][4] = { {13, 15, 26, 6}, {17, 29, 16, 24} };
    uint32_t x0 = c0 + ks[0], x1 = c1 + ks[1];
    for (int g = 0; g < 5; ++g) {
        const int* rr = rot[g & 1];
        for (int i = 0; i < 4; ++i) {
            x0 += x1; x1 = rotl32(x1, rr[i]); x1 ^= x0;
        }
        x0 += ks[(g + 1) % 3];
        x1 += ks[(g + 2) % 3] + (uint32_t)(g + 1);
    }
    *o0 = x0; *o1 = x1;
}

static void compute_perm(int* perm76)
{
    uint32_t s0, s1;
    threefry2x32_host(0u, 42u, 0u, 1u, &s0, &s1);   // foldlike split of key(42)

    static uint32_t keys[NUNSEL];
    static int idx[NUNSEL];
    for (int i = 0; i < NUNSEL; ++i) {
        uint32_t o0, o1;
        threefry2x32_host(s0, s1, 0u, (uint32_t)i, &o0, &o1);
        keys[i] = o0 ^ o1;                           // partitionable random_bits
        idx[i] = i;
    }
    std::stable_sort(idx, idx + NUNSEL,
                     [](int a, int b) { return keys[a] < keys[b]; });
    for (int j = 0; j < NREM; ++j) perm76[j] = idx[j];
}

extern "C" void kernel_launch(void* const* d_in, const int* in_sizes, int n_in,
                              void* d_out, int out_size)
{
    const float* feat = (const float*)d_in[0];   // (8,16,384,32,32)
    const float* dw_w = (const float*)d_in[1];   // (384,1,3,3)
    // d_in[2] = dw_b (constant shift, irrelevant to ranking)
    const float* pw_w = (const float*)d_in[3];   // (1,384,1,1)
    // d_in[4] = pw_b (constant shift, irrelevant)

    Perm76 perm;
    compute_perm(perm.v);   // deterministic, host-side, capture-time only

    dim3 grid(NG, NROWS);
    fused_kernel<<<grid, 256>>>(feat, dw_w, pw_w, (float*)d_out, perm);
}